// round 2
// baseline (speedup 1.0000x reference)
#include <cuda_runtime.h>
#include <math.h>

#define BB  8
#define SS  2048
#define DD  1024
#define DKK 128

// Scratch for projected Q, K, V (allocation-free rule: __device__ globals)
static __device__ float g_Q[BB * SS * DKK];
static __device__ float g_K[BB * SS * DKK];
static __device__ float g_V[BB * SS * DKK];

// ---------------------------------------------------------------------------
// Projection: Out[m, n] = sum_k A[m, k] * W[n, k], masked rows (t >= len) -> 0
// A is [16384, 1024] (x or context), W is [128, 1024] (torch Linear layout).
// 128x128 block tile, BK=8, 256 threads, 8x8 per-thread tile.
// ---------------------------------------------------------------------------
__global__ __launch_bounds__(256, 2) void proj_kernel(
    const float* __restrict__ x, const float* __restrict__ ctx,
    const float* __restrict__ Wq, const float* __restrict__ Wk,
    const float* __restrict__ Wv, const int* __restrict__ lens)
{
    __shared__ float sA[8][132];   // k-major: sA[k][m]
    __shared__ float sB[8][132];   // k-major: sB[k][n]

    const int which = blockIdx.y;                       // 0=Q, 1=K, 2=V
    const float* A  = (which == 2) ? x : ctx;
    const float* W  = (which == 0) ? Wq : (which == 1) ? Wk : Wv;
    float* Out      = (which == 0) ? g_Q : (which == 1) ? g_K : g_V;

    const int tid  = threadIdx.x;
    const int tx   = tid & 15;
    const int ty   = tid >> 4;
    const int m0   = blockIdx.x * 128;
    const int lrow = tid >> 1;          // 0..127
    const int lk4  = (tid & 1) << 2;    // 0 or 4

    const float* Ap = A + (size_t)(m0 + lrow) * DD + lk4;
    const float* Wp = W + (size_t)lrow * DD + lk4;

    float acc[8][8];
#pragma unroll
    for (int i = 0; i < 8; i++)
#pragma unroll
        for (int j = 0; j < 8; j++) acc[i][j] = 0.f;

    for (int k0 = 0; k0 < DD; k0 += 8) {
        float4 av = *(const float4*)(Ap + k0);
        float4 bv = *(const float4*)(Wp + k0);
        __syncthreads();
        sA[lk4 + 0][lrow] = av.x; sA[lk4 + 1][lrow] = av.y;
        sA[lk4 + 2][lrow] = av.z; sA[lk4 + 3][lrow] = av.w;
        sB[lk4 + 0][lrow] = bv.x; sB[lk4 + 1][lrow] = bv.y;
        sB[lk4 + 2][lrow] = bv.z; sB[lk4 + 3][lrow] = bv.w;
        __syncthreads();
#pragma unroll
        for (int k = 0; k < 8; k++) {
            float a[8], bb[8];
            *(float4*)a        = *(const float4*)&sA[k][ty * 8];
            *(float4*)(a + 4)  = *(const float4*)&sA[k][ty * 8 + 4];
            *(float4*)bb       = *(const float4*)&sB[k][tx * 8];
            *(float4*)(bb + 4) = *(const float4*)&sB[k][tx * 8 + 4];
#pragma unroll
            for (int i = 0; i < 8; i++)
#pragma unroll
                for (int j = 0; j < 8; j++)
                    acc[i][j] = fmaf(a[i], bb[j], acc[i][j]);
        }
    }

    const int batch = m0 / SS;   // 2048 % 128 == 0: block fully inside one batch
    const int len   = lens[batch];
#pragma unroll
    for (int i = 0; i < 8; i++) {
        const int row  = m0 + ty * 8 + i;
        const float msk = ((row - batch * SS) < len) ? 1.f : 0.f;
        float4 o0 = make_float4(acc[i][0] * msk, acc[i][1] * msk,
                                acc[i][2] * msk, acc[i][3] * msk);
        float4 o1 = make_float4(acc[i][4] * msk, acc[i][5] * msk,
                                acc[i][6] * msk, acc[i][7] * msk);
        float* op = Out + (size_t)row * DKK + tx * 8;
        *(float4*)op       = o0;
        *(float4*)(op + 4) = o1;
    }
}

// ---------------------------------------------------------------------------
// Flash attention (fp32): 64-query x 64-key tiles, dk = 128.
// Online softmax with causal (j <= t) and length (j < len) masks.
// Threads: 16x16; energy stage per-thread 4x4, PV stage per-thread 4 rows x 8 cols.
// ---------------------------------------------------------------------------
#define ATTN_SMEM_BYTES ((128 * 68 * 2 + 64 * 128 + 64 * 72) * 4)   // 120832

__global__ __launch_bounds__(256, 1) void attn_kernel(const int* __restrict__ lens,
                                                      float* __restrict__ out)
{
    extern __shared__ float sm[];
    float* sQ = sm;                  // [128][68]  k-major
    float* sK = sm + 128 * 68;       // [128][68]  k-major
    float* sV = sK + 128 * 68;       // [64][128]  natural
    float* sP = sV + 64 * 128;       // [64][72]   j-major

    const int b   = blockIdx.y;
    const int qt  = (gridDim.x - 1) - blockIdx.x;   // big tiles first (causal balance)
    const int q0  = qt * 64;
    const int len = lens[b];
    const int tid = threadIdx.x;
    const int tx  = tid & 15;
    const int ty  = tid >> 4;

    const float* Qg = g_Q + (size_t)b * SS * DKK;
    const float* Kg = g_K + (size_t)b * SS * DKK;
    const float* Vg = g_V + (size_t)b * SS * DKK;

    // Load Q tile (64 x 128) transposed into sQ[k][r]
#pragma unroll
    for (int l = 0; l < 8; l++) {
        int f   = l * 256 + tid;
        int row = f >> 5;
        int c4  = (f & 31) << 2;
        float4 q = *(const float4*)(Qg + (size_t)(q0 + row) * DKK + c4);
        sQ[(c4 + 0) * 68 + row] = q.x;
        sQ[(c4 + 1) * 68 + row] = q.y;
        sQ[(c4 + 2) * 68 + row] = q.z;
        sQ[(c4 + 3) * 68 + row] = q.w;
    }

    float m_i[4], l_i[4], acc[4][8];
#pragma unroll
    for (int i = 0; i < 4; i++) { m_i[i] = -1e30f; l_i[i] = 0.f; }
#pragma unroll
    for (int i = 0; i < 4; i++)
#pragma unroll
        for (int c = 0; c < 8; c++) acc[i][c] = 0.f;

    const int jt_max   = min(qt, (len - 1) >> 6);
    const float scale  = 0.08838834764831845f;   // 1/sqrt(128)

    for (int jt = 0; jt <= jt_max; jt++) {
        const int j0 = jt * 64;
        __syncthreads();
        // Load K tile transposed + V tile natural
#pragma unroll
        for (int l = 0; l < 8; l++) {
            int f   = l * 256 + tid;
            int row = f >> 5;
            int c4  = (f & 31) << 2;
            size_t g = (size_t)(j0 + row) * DKK + c4;
            float4 kv = *(const float4*)(Kg + g);
            sK[(c4 + 0) * 68 + row] = kv.x;
            sK[(c4 + 1) * 68 + row] = kv.y;
            sK[(c4 + 2) * 68 + row] = kv.z;
            sK[(c4 + 3) * 68 + row] = kv.w;
            float4 vv = *(const float4*)(Vg + g);
            *(float4*)(sV + row * 128 + c4) = vv;
        }
        __syncthreads();

        // Energy tile: e[i][j] = Q[q0+ty*4+i] . K[j0+tx*4+j]
        float e[4][4];
#pragma unroll
        for (int i = 0; i < 4; i++)
#pragma unroll
            for (int j = 0; j < 4; j++) e[i][j] = 0.f;

#pragma unroll 8
        for (int k = 0; k < 128; k++) {
            float qv[4], kv[4];
            *(float4*)qv = *(const float4*)(sQ + k * 68 + ty * 4);
            *(float4*)kv = *(const float4*)(sK + k * 68 + tx * 4);
#pragma unroll
            for (int i = 0; i < 4; i++)
#pragma unroll
                for (int j = 0; j < 4; j++)
                    e[i][j] = fmaf(qv[i], kv[j], e[i][j]);
        }

        // Scale + masks + online softmax (row reductions across the 16 tx lanes)
        float fac[4];
#pragma unroll
        for (int i = 0; i < 4; i++) {
            const int r = q0 + ty * 4 + i;
#pragma unroll
            for (int j = 0; j < 4; j++) {
                const int jg = j0 + tx * 4 + j;
                e[i][j] = (jg <= r && jg < len) ? e[i][j] * scale : -1e30f;
            }
            float mx = fmaxf(fmaxf(e[i][0], e[i][1]), fmaxf(e[i][2], e[i][3]));
#pragma unroll
            for (int o = 8; o >= 1; o >>= 1)
                mx = fmaxf(mx, __shfl_xor_sync(0xffffffffu, mx, o));
            const float mnew = fmaxf(m_i[i], mx);
            fac[i] = __expf(m_i[i] - mnew);
            m_i[i] = mnew;
            float s = 0.f;
#pragma unroll
            for (int j = 0; j < 4; j++) {
                e[i][j] = __expf(e[i][j] - mnew);
                s += e[i][j];
            }
#pragma unroll
            for (int o = 8; o >= 1; o >>= 1)
                s += __shfl_xor_sync(0xffffffffu, s, o);
            l_i[i] = l_i[i] * fac[i] + s;
        }

        // P -> shared, j-major
#pragma unroll
        for (int j = 0; j < 4; j++) {
            float4 pv = make_float4(e[0][j], e[1][j], e[2][j], e[3][j]);
            *(float4*)(sP + (tx * 4 + j) * 72 + ty * 4) = pv;
        }
        __syncthreads();

        // Rescale accumulators, then acc += P @ V
#pragma unroll
        for (int i = 0; i < 4; i++)
#pragma unroll
            for (int c = 0; c < 8; c++) acc[i][c] *= fac[i];

#pragma unroll 4
        for (int j = 0; j < 64; j++) {
            float pv[4], vv[8];
            *(float4*)pv       = *(const float4*)(sP + j * 72 + ty * 4);
            *(float4*)vv       = *(const float4*)(sV + j * 128 + tx * 8);
            *(float4*)(vv + 4) = *(const float4*)(sV + j * 128 + tx * 8 + 4);
#pragma unroll
            for (int i = 0; i < 4; i++)
#pragma unroll
                for (int c = 0; c < 8; c++)
                    acc[i][c] = fmaf(pv[i], vv[c], acc[i][c]);
        }
    }

    // Epilogue: out = acc / l
#pragma unroll
    for (int i = 0; i < 4; i++) {
        const float inv = 1.f / l_i[i];
        const int row = q0 + ty * 4 + i;
        float4 o0 = make_float4(acc[i][0] * inv, acc[i][1] * inv,
                                acc[i][2] * inv, acc[i][3] * inv);
        float4 o1 = make_float4(acc[i][4] * inv, acc[i][5] * inv,
                                acc[i][6] * inv, acc[i][7] * inv);
        float* op = out + ((size_t)b * SS + row) * DKK + tx * 8;
        *(float4*)op       = o0;
        *(float4*)(op + 4) = o1;
    }
}

// ---------------------------------------------------------------------------
extern "C" void kernel_launch(void* const* d_in, const int* in_sizes, int n_in,
                              void* d_out, int out_size)
{
    const float* x   = (const float*)d_in[0];
    const float* ctx = (const float*)d_in[1];
    const float* Wq  = (const float*)d_in[2];
    const float* Wk  = (const float*)d_in[3];
    const float* Wv  = (const float*)d_in[4];
    const int* lens  = (const int*)d_in[5];
    float* out = (float*)d_out;

    cudaFuncSetAttribute(attn_kernel, cudaFuncAttributeMaxDynamicSharedMemorySize,
                         ATTN_SMEM_BYTES);

    dim3 gp(BB * SS / 128, 3);
    proj_kernel<<<gp, 256>>>(x, ctx, Wq, Wk, Wv, lens);

    dim3 ga(SS / 64, BB);
    attn_kernel<<<ga, 256, ATTN_SMEM_BYTES>>>(lens, out);
}

// round 5
// speedup vs baseline: 2.8463x; 2.8463x over previous
#include <cuda_runtime.h>
#include <cuda_bf16.h>
#include <math.h>
#include <stdint.h>

#define BB   8
#define SS   2048
#define DD   1024
#define DKK  128
#define NTOK (BB * SS)          // 16384

// ---------------------------------------------------------------------------
// Scratch (allocation-free rule: __device__ globals)
// ---------------------------------------------------------------------------
static __device__ __nv_bfloat16 g_ch[NTOK * DD], g_cl[NTOK * DD];   // ctx hi/lo
static __device__ __nv_bfloat16 g_xh[NTOK * DD], g_xl[NTOK * DD];   // x   hi/lo
static __device__ __nv_bfloat16 g_Wh[3 * DKK * DD], g_Wl[3 * DKK * DD];
static __device__ __nv_bfloat16 g_Qh[NTOK * DKK], g_Ql[NTOK * DKK];
static __device__ __nv_bfloat16 g_Kh[NTOK * DKK], g_Kl[NTOK * DKK];
static __device__ __nv_bfloat16 g_Vh[NTOK * DKK], g_Vl[NTOK * DKK];

// ---------------------------------------------------------------------------
// Helpers: ldmatrix / mma.sync (sm_80+ features, safe for sm_103 target)
// ---------------------------------------------------------------------------
__device__ __forceinline__ uint32_t smem_u32(const void* p) {
    uint32_t a;
    asm("{ .reg .u64 t; cvta.to.shared.u64 t, %1; cvt.u32.u64 %0, t; }"
        : "=r"(a) : "l"(p));
    return a;
}

__device__ __forceinline__ void ldsm4(uint32_t r[4], uint32_t addr) {
    asm volatile("ldmatrix.sync.aligned.m8n8.x4.shared.b16 {%0,%1,%2,%3}, [%4];"
                 : "=r"(r[0]), "=r"(r[1]), "=r"(r[2]), "=r"(r[3]) : "r"(addr));
}
__device__ __forceinline__ void ldsm4t(uint32_t r[4], uint32_t addr) {
    asm volatile("ldmatrix.sync.aligned.m8n8.x4.trans.shared.b16 {%0,%1,%2,%3}, [%4];"
                 : "=r"(r[0]), "=r"(r[1]), "=r"(r[2]), "=r"(r[3]) : "r"(addr));
}
__device__ __forceinline__ void mma16816(float c[4], const uint32_t a[4],
                                         uint32_t b0, uint32_t b1) {
    asm volatile(
        "mma.sync.aligned.m16n8k16.row.col.f32.bf16.bf16.f32 "
        "{%0,%1,%2,%3}, {%4,%5,%6,%7}, {%8,%9}, {%0,%1,%2,%3};"
        : "+f"(c[0]), "+f"(c[1]), "+f"(c[2]), "+f"(c[3])
        : "r"(a[0]), "r"(a[1]), "r"(a[2]), "r"(a[3]), "r"(b0), "r"(b1));
}

__device__ __forceinline__ uint32_t pack2(float lo, float hi) {
    __nv_bfloat162 t = __floats2bfloat162_rn(lo, hi);
    return *reinterpret_cast<uint32_t*>(&t);
}
// Dekker split of a float pair into packed bf16x2 hi + lo residual
__device__ __forceinline__ void split2(float f0, float f1, uint32_t& h, uint32_t& l) {
    __nv_bfloat162 t = __floats2bfloat162_rn(f0, f1);
    h = *reinterpret_cast<uint32_t*>(&t);
    float r0 = __low2float(t), r1 = __high2float(t);
    __nv_bfloat162 u = __floats2bfloat162_rn(f0 - r0, f1 - r1);
    l = *reinterpret_cast<uint32_t*>(&u);
}

// ---------------------------------------------------------------------------
// Kernel 1: elementwise split of ctx, x, W into hi/lo bf16
// ---------------------------------------------------------------------------
#define N1 ((long long)NTOK * DD)          // 16777216
#define WN ((long long)DKK * DD)           // 131072

__global__ void convert_kernel(const float* __restrict__ x,
                               const float* __restrict__ ctx,
                               const float* __restrict__ Wq,
                               const float* __restrict__ Wk,
                               const float* __restrict__ Wv) {
    const long long total4 = (2 * N1 + 3 * WN) >> 2;
    for (long long i = (long long)blockIdx.x * blockDim.x + threadIdx.x;
         i < total4; i += (long long)gridDim.x * blockDim.x) {
        const long long e = i << 2;
        const float* src;
        __nv_bfloat16 *dh, *dl;
        if (e < N1)           { src = ctx + e;      dh = g_ch + e;      dl = g_cl + e; }
        else if (e < 2 * N1)  { long long o = e - N1;
                                src = x + o;        dh = g_xh + o;      dl = g_xl + o; }
        else {
            long long o = e - 2 * N1;
            dh = g_Wh + o; dl = g_Wl + o;
            if (o < WN)          src = Wq + o;
            else if (o < 2 * WN) src = Wk + (o - WN);
            else                 src = Wv + (o - 2 * WN);
        }
        float4 v = *(const float4*)src;
        uint32_t h0, l0, h1, l1;
        split2(v.x, v.y, h0, l0);
        split2(v.z, v.w, h1, l1);
        *(uint2*)dh = make_uint2(h0, h1);
        *(uint2*)dl = make_uint2(l0, l1);
    }
}

// ---------------------------------------------------------------------------
// Kernel 2: projection GEMM  Out[m,n] = sum_k A[m,k] * W[n,k]  (bf16x3 HMMA)
// CTA: 128 m-rows x full N=128, K chunks of 64. 256 threads (8 warps, 32x64).
// ---------------------------------------------------------------------------
#define PLD 72                                // smem stride (bf16 elems)
#define PROJ_SMEM (4 * 128 * PLD * 2)         // 73728 B

__global__ __launch_bounds__(256, 2) void proj_tc(const int* __restrict__ lens) {
    extern __shared__ __nv_bfloat16 psm[];
    __nv_bfloat16* sAh = psm;
    __nv_bfloat16* sAl = psm + 128 * PLD;
    __nv_bfloat16* sWh = psm + 2 * 128 * PLD;
    __nv_bfloat16* sWl = psm + 3 * 128 * PLD;
    const uint32_t aAh = smem_u32(sAh), aAl = smem_u32(sAl);
    const uint32_t aWh = smem_u32(sWh), aWl = smem_u32(sWl);

    const int which = blockIdx.y;                         // 0=Q,1=K,2=V
    const int m0cta = blockIdx.x * 128;
    const __nv_bfloat16* Ah = (which == 2) ? g_xh : g_ch;
    const __nv_bfloat16* Al = (which == 2) ? g_xl : g_cl;
    const __nv_bfloat16* Wh = g_Wh + (size_t)which * WN;
    const __nv_bfloat16* Wl = g_Wl + (size_t)which * WN;
    __nv_bfloat16* Oh = (which == 0) ? g_Qh : (which == 1) ? g_Kh : g_Vh;
    __nv_bfloat16* Ol = (which == 0) ? g_Ql : (which == 1) ? g_Kl : g_Vl;

    const int tid = threadIdx.x;
    const int w = tid >> 5, l = tid & 31;
    const int m0 = (w & 3) * 32;              // warp m offset
    const int n0 = (w >> 2) * 64;             // warp n offset

    const int arow = (l & 7) + 8 * ((l >> 3) & 1);   // A-operand lane row
    const int acol = 8 * (l >> 4);                   // A-operand lane col
    const int brow = (l & 7) + 8 * (l >> 4);         // B-operand lane row
    const int bcol = 8 * ((l >> 3) & 1);             // B-operand lane col

    float c[2][8][4];
#pragma unroll
    for (int mf = 0; mf < 2; mf++)
#pragma unroll
        for (int nf = 0; nf < 8; nf++)
#pragma unroll
            for (int e = 0; e < 4; e++) c[mf][nf][e] = 0.f;

    for (int kc = 0; kc < 16; kc++) {
        const int kg = kc * 64;
        __syncthreads();
        // Load 128x64 chunks of A(hi/lo) and W(hi/lo); 8 uint4 per row.
#pragma unroll
        for (int i = 0; i < 4; i++) {
            const int idx = i * 256 + tid;
            const int r = idx >> 3, cc = (idx & 7) * 8;
            const size_t ga = (size_t)(m0cta + r) * DD + kg + cc;
            const size_t gw = (size_t)r * DD + kg + cc;
            *(uint4*)(sAh + r * PLD + cc) = *(const uint4*)(Ah + ga);
            *(uint4*)(sAl + r * PLD + cc) = *(const uint4*)(Al + ga);
            *(uint4*)(sWh + r * PLD + cc) = *(const uint4*)(Wh + gw);
            *(uint4*)(sWl + r * PLD + cc) = *(const uint4*)(Wl + gw);
        }
        __syncthreads();

#pragma unroll
        for (int ks = 0; ks < 4; ks++) {
            const int k0 = ks * 16;
            uint32_t ah[2][4], al[2][4];
#pragma unroll
            for (int mf = 0; mf < 2; mf++) {
                const uint32_t off = 2u * ((m0 + mf * 16 + arow) * PLD + k0 + acol);
                ldsm4(ah[mf], aAh + off);
                ldsm4(al[mf], aAl + off);
            }
#pragma unroll
            for (int bb = 0; bb < 4; bb++) {
                uint32_t bh[4], bl[4];
                const uint32_t off = 2u * ((n0 + bb * 16 + brow) * PLD + k0 + bcol);
                ldsm4(bh, aWh + off);
                ldsm4(bl, aWl + off);
#pragma unroll
                for (int mf = 0; mf < 2; mf++) {
                    mma16816(c[mf][2 * bb], ah[mf], bh[0], bh[1]);
                    mma16816(c[mf][2 * bb], ah[mf], bl[0], bl[1]);
                    mma16816(c[mf][2 * bb], al[mf], bh[0], bh[1]);
                    mma16816(c[mf][2 * bb + 1], ah[mf], bh[2], bh[3]);
                    mma16816(c[mf][2 * bb + 1], ah[mf], bl[2], bl[3]);
                    mma16816(c[mf][2 * bb + 1], al[mf], bh[2], bh[3]);
                }
            }
        }
    }

    // Epilogue: mask padded rows, split to bf16 hi/lo, store.
    const int batch = m0cta >> 11;
    const int len = lens[batch];
    const int tokbase = m0cta - (batch << 11);
#pragma unroll
    for (int mf = 0; mf < 2; mf++) {
        const int lr = m0 + mf * 16 + (l >> 2);
        const int gm0 = m0cta + lr, gm1 = gm0 + 8;
        const float msk0 = (tokbase + lr < len) ? 1.f : 0.f;
        const float msk1 = (tokbase + lr + 8 < len) ? 1.f : 0.f;
#pragma unroll
        for (int nf = 0; nf < 8; nf++) {
            const int col = n0 + nf * 8 + 2 * (l & 3);
            uint32_t h, lo;
            split2(c[mf][nf][0] * msk0, c[mf][nf][1] * msk0, h, lo);
            *(uint32_t*)(Oh + (size_t)gm0 * DKK + col) = h;
            *(uint32_t*)(Ol + (size_t)gm0 * DKK + col) = lo;
            split2(c[mf][nf][2] * msk1, c[mf][nf][3] * msk1, h, lo);
            *(uint32_t*)(Oh + (size_t)gm1 * DKK + col) = h;
            *(uint32_t*)(Ol + (size_t)gm1 * DKK + col) = lo;
        }
    }
}

// ---------------------------------------------------------------------------
// Kernel 3: flash attention, bf16x3 HMMA, register-resident softmax & P.
// CTA: 64 queries, key tiles of 64, dk=128. 128 threads (4 warps x 16 rows).
// ---------------------------------------------------------------------------
#define ALD 136                               // smem stride (bf16 elems)
#define TSZ (64 * ALD)                        // one tile, elems
#define ATTN_SMEM (6 * TSZ * 2)               // 104448 B

__global__ __launch_bounds__(128, 2) void attn_tc(const int* __restrict__ lens,
                                                  float* __restrict__ out) {
    extern __shared__ __nv_bfloat16 asm_[];
    __nv_bfloat16* sQh = asm_;
    __nv_bfloat16* sQl = asm_ + TSZ;
    __nv_bfloat16* sKh = asm_ + 2 * TSZ;
    __nv_bfloat16* sKl = asm_ + 3 * TSZ;
    __nv_bfloat16* sVh = asm_ + 4 * TSZ;
    __nv_bfloat16* sVl = asm_ + 5 * TSZ;
    const uint32_t aQh = smem_u32(sQh), aQl = smem_u32(sQl);
    const uint32_t aKh = smem_u32(sKh), aKl = smem_u32(sKl);
    const uint32_t aVh = smem_u32(sVh), aVl = smem_u32(sVl);

    const int b = blockIdx.y;
    const int qt = (gridDim.x - 1) - blockIdx.x;   // big tiles first
    const int q0 = qt * 64;
    const int len = lens[b];
    const int tid = threadIdx.x;
    const int w = tid >> 5, l = tid & 31;
    const int m0 = w * 16;

    const int arow = (l & 7) + 8 * ((l >> 3) & 1);
    const int acol = 8 * (l >> 4);
    const int brow = (l & 7) + 8 * (l >> 4);
    const int bcol = 8 * ((l >> 3) & 1);

    // Load Q tile (64 x 128) hi/lo
#pragma unroll
    for (int i = 0; i < 8; i++) {
        const int idx = i * 128 + tid;
        const int r = idx >> 4, cc = (idx & 15) * 8;
        const size_t g = (size_t)(b * SS + q0 + r) * DKK + cc;
        *(uint4*)(sQh + r * ALD + cc) = *(const uint4*)(g_Qh + g);
        *(uint4*)(sQl + r * ALD + cc) = *(const uint4*)(g_Ql + g);
    }

    float o[16][4];
#pragma unroll
    for (int nf = 0; nf < 16; nf++)
#pragma unroll
        for (int e = 0; e < 4; e++) o[nf][e] = 0.f;
    float mI0 = -1e30f, mI1 = -1e30f, lI0 = 0.f, lI1 = 0.f;

    const int r0 = q0 + m0 + (l >> 2);
    const int r1 = r0 + 8;
    const int jt_max = min(qt, (len - 1) >> 6);
    const float scale = 0.08838834764831845f;      // 1/sqrt(128)

    for (int jt = 0; jt <= jt_max; jt++) {
        const int j0 = jt * 64;
        __syncthreads();
        // Load K/V tiles (64 x 128) hi/lo
#pragma unroll
        for (int i = 0; i < 8; i++) {
            const int idx = i * 128 + tid;
            const int r = idx >> 4, cc = (idx & 15) * 8;
            const size_t g = (size_t)(b * SS + j0 + r) * DKK + cc;
            *(uint4*)(sKh + r * ALD + cc) = *(const uint4*)(g_Kh + g);
            *(uint4*)(sKl + r * ALD + cc) = *(const uint4*)(g_Kl + g);
            *(uint4*)(sVh + r * ALD + cc) = *(const uint4*)(g_Vh + g);
            *(uint4*)(sVl + r * ALD + cc) = *(const uint4*)(g_Vl + g);
        }
        __syncthreads();

        // ---- S = Q K^T (3-term split) ----
        float s[8][4];
#pragma unroll
        for (int nf = 0; nf < 8; nf++)
#pragma unroll
            for (int e = 0; e < 4; e++) s[nf][e] = 0.f;

#pragma unroll
        for (int ks = 0; ks < 8; ks++) {
            const int k0 = ks * 16;
            uint32_t ah[4], al[4];
            const uint32_t offA = 2u * ((m0 + arow) * ALD + k0 + acol);
            ldsm4(ah, aQh + offA);
            ldsm4(al, aQl + offA);
#pragma unroll
            for (int bb = 0; bb < 4; bb++) {
                uint32_t bh[4], bl[4];
                const uint32_t offB = 2u * ((bb * 16 + brow) * ALD + k0 + bcol);
                ldsm4(bh, aKh + offB);
                ldsm4(bl, aKl + offB);
                mma16816(s[2 * bb], ah, bh[0], bh[1]);
                mma16816(s[2 * bb], ah, bl[0], bl[1]);
                mma16816(s[2 * bb], al, bh[0], bh[1]);
                mma16816(s[2 * bb + 1], ah, bh[2], bh[3]);
                mma16816(s[2 * bb + 1], ah, bl[2], bl[3]);
                mma16816(s[2 * bb + 1], al, bh[2], bh[3]);
            }
        }

        // ---- scale + masks ----
        if (j0 + 63 <= q0 && j0 + 63 < len) {
#pragma unroll
            for (int nf = 0; nf < 8; nf++)
#pragma unroll
                for (int e = 0; e < 4; e++) s[nf][e] *= scale;
        } else {
#pragma unroll
            for (int nf = 0; nf < 8; nf++) {
                const int cj = j0 + nf * 8 + 2 * (l & 3);
                s[nf][0] = (cj     <= r0 && cj     < len) ? s[nf][0] * scale : -1e30f;
                s[nf][1] = (cj + 1 <= r0 && cj + 1 < len) ? s[nf][1] * scale : -1e30f;
                s[nf][2] = (cj     <= r1 && cj     < len) ? s[nf][2] * scale : -1e30f;
                s[nf][3] = (cj + 1 <= r1 && cj + 1 < len) ? s[nf][3] * scale : -1e30f;
            }
        }

        // ---- online softmax (register rows; reduce across quad lanes) ----
        float mx0 = -1e30f, mx1 = -1e30f;
#pragma unroll
        for (int nf = 0; nf < 8; nf++) {
            mx0 = fmaxf(mx0, fmaxf(s[nf][0], s[nf][1]));
            mx1 = fmaxf(mx1, fmaxf(s[nf][2], s[nf][3]));
        }
        mx0 = fmaxf(mx0, __shfl_xor_sync(0xffffffffu, mx0, 1));
        mx0 = fmaxf(mx0, __shfl_xor_sync(0xffffffffu, mx0, 2));
        mx1 = fmaxf(mx1, __shfl_xor_sync(0xffffffffu, mx1, 1));
        mx1 = fmaxf(mx1, __shfl_xor_sync(0xffffffffu, mx1, 2));

        const float mn0 = fmaxf(mI0, mx0), mn1 = fmaxf(mI1, mx1);
        const float f0 = __expf(mI0 - mn0), f1 = __expf(mI1 - mn1);
        mI0 = mn0; mI1 = mn1;

        float sum0 = 0.f, sum1 = 0.f;
#pragma unroll
        for (int nf = 0; nf < 8; nf++) {
            s[nf][0] = __expf(s[nf][0] - mn0);
            s[nf][1] = __expf(s[nf][1] - mn0);
            s[nf][2] = __expf(s[nf][2] - mn1);
            s[nf][3] = __expf(s[nf][3] - mn1);
            sum0 += s[nf][0] + s[nf][1];
            sum1 += s[nf][2] + s[nf][3];
        }
        sum0 += __shfl_xor_sync(0xffffffffu, sum0, 1);
        sum0 += __shfl_xor_sync(0xffffffffu, sum0, 2);
        sum1 += __shfl_xor_sync(0xffffffffu, sum1, 1);
        sum1 += __shfl_xor_sync(0xffffffffu, sum1, 2);
        lI0 = lI0 * f0 + sum0;
        lI1 = lI1 * f1 + sum1;

        // rescale output accumulators
#pragma unroll
        for (int nf = 0; nf < 16; nf++) {
            o[nf][0] *= f0; o[nf][1] *= f0;
            o[nf][2] *= f1; o[nf][3] *= f1;
        }

        // pack P into A-fragments (c-layout == a-layout), hi + lo
        uint32_t Ph[4][4], Pl[4][4];
#pragma unroll
        for (int t = 0; t < 4; t++) {
            split2(s[2 * t][0],     s[2 * t][1],     Ph[t][0], Pl[t][0]);
            split2(s[2 * t][2],     s[2 * t][3],     Ph[t][1], Pl[t][1]);
            split2(s[2 * t + 1][0], s[2 * t + 1][1], Ph[t][2], Pl[t][2]);
            split2(s[2 * t + 1][2], s[2 * t + 1][3], Ph[t][3], Pl[t][3]);
        }

        // ---- O += P V (3-term split, V via ldmatrix.trans) ----
#pragma unroll
        for (int t = 0; t < 4; t++) {
            const int jr = t * 16;
#pragma unroll
            for (int db = 0; db < 8; db++) {
                uint32_t vh[4], vl[4];
                const uint32_t offV = 2u * ((jr + arow) * ALD + db * 16 + acol);
                ldsm4t(vh, aVh + offV);
                ldsm4t(vl, aVl + offV);
                mma16816(o[2 * db], Ph[t], vh[0], vh[1]);
                mma16816(o[2 * db], Ph[t], vl[0], vl[1]);
                mma16816(o[2 * db], Pl[t], vh[0], vh[1]);
                mma16816(o[2 * db + 1], Ph[t], vh[2], vh[3]);
                mma16816(o[2 * db + 1], Ph[t], vl[2], vl[3]);
                mma16816(o[2 * db + 1], Pl[t], vh[2], vh[3]);
            }
        }
    }

    // ---- epilogue: O /= l ----
    const float inv0 = 1.f / lI0, inv1 = 1.f / lI1;
#pragma unroll
    for (int nf = 0; nf < 16; nf++) {
        const int col = nf * 8 + 2 * (l & 3);
        *(float2*)(out + ((size_t)b * SS + r0) * DKK + col) =
            make_float2(o[nf][0] * inv0, o[nf][1] * inv0);
        *(float2*)(out + ((size_t)b * SS + r1) * DKK + col) =
            make_float2(o[nf][2] * inv1, o[nf][3] * inv1);
    }
}

// ---------------------------------------------------------------------------
extern "C" void kernel_launch(void* const* d_in, const int* in_sizes, int n_in,
                              void* d_out, int out_size)
{
    const float* x   = (const float*)d_in[0];
    const float* ctx = (const float*)d_in[1];
    const float* Wq  = (const float*)d_in[2];
    const float* Wk  = (const float*)d_in[3];
    const float* Wv  = (const float*)d_in[4];
    const int* lens  = (const int*)d_in[5];
    float* out = (float*)d_out;

    cudaFuncSetAttribute(proj_tc, cudaFuncAttributeMaxDynamicSharedMemorySize,
                         PROJ_SMEM);
    cudaFuncSetAttribute(attn_tc, cudaFuncAttributeMaxDynamicSharedMemorySize,
                         ATTN_SMEM);

    convert_kernel<<<4096, 256>>>(x, ctx, Wq, Wk, Wv);

    dim3 gp(NTOK / 128, 3);
    proj_tc<<<gp, 256, PROJ_SMEM>>>(lens);

    dim3 ga(SS / 64, BB);
    attn_tc<<<ga, 128, ATTN_SMEM>>>(lens, out);
}

// round 6
// speedup vs baseline: 3.6126x; 1.2692x over previous
#include <cuda_runtime.h>
#include <cuda_bf16.h>
#include <math.h>
#include <stdint.h>

#define BB   8
#define SS   2048
#define DD   1024
#define DKK  128
#define NTOK (BB * SS)          // 16384

// ---------------------------------------------------------------------------
// Scratch (allocation-free rule: __device__ globals)
// ---------------------------------------------------------------------------
static __device__ __nv_bfloat16 g_Wh[3 * DKK * DD], g_Wl[3 * DKK * DD];
static __device__ __nv_bfloat16 g_Qh[NTOK * DKK], g_Ql[NTOK * DKK];
static __device__ __nv_bfloat16 g_Kh[NTOK * DKK], g_Kl[NTOK * DKK];
static __device__ __nv_bfloat16 g_Vh[NTOK * DKK], g_Vl[NTOK * DKK];

// ---------------------------------------------------------------------------
// Helpers: ldmatrix / mma.sync (sm_80+ features, safe for sm_103 target)
// ---------------------------------------------------------------------------
__device__ __forceinline__ uint32_t smem_u32(const void* p) {
    uint32_t a;
    asm("{ .reg .u64 t; cvta.to.shared.u64 t, %1; cvt.u32.u64 %0, t; }"
        : "=r"(a) : "l"(p));
    return a;
}

__device__ __forceinline__ void ldsm4(uint32_t r[4], uint32_t addr) {
    asm volatile("ldmatrix.sync.aligned.m8n8.x4.shared.b16 {%0,%1,%2,%3}, [%4];"
                 : "=r"(r[0]), "=r"(r[1]), "=r"(r[2]), "=r"(r[3]) : "r"(addr));
}
__device__ __forceinline__ void ldsm4t(uint32_t r[4], uint32_t addr) {
    asm volatile("ldmatrix.sync.aligned.m8n8.x4.trans.shared.b16 {%0,%1,%2,%3}, [%4];"
                 : "=r"(r[0]), "=r"(r[1]), "=r"(r[2]), "=r"(r[3]) : "r"(addr));
}
__device__ __forceinline__ void mma16816(float c[4], const uint32_t a[4],
                                         uint32_t b0, uint32_t b1) {
    asm volatile(
        "mma.sync.aligned.m16n8k16.row.col.f32.bf16.bf16.f32 "
        "{%0,%1,%2,%3}, {%4,%5,%6,%7}, {%8,%9}, {%0,%1,%2,%3};"
        : "+f"(c[0]), "+f"(c[1]), "+f"(c[2]), "+f"(c[3])
        : "r"(a[0]), "r"(a[1]), "r"(a[2]), "r"(a[3]), "r"(b0), "r"(b1));
}

// Dekker split of a float pair into packed bf16x2 hi + lo residual
__device__ __forceinline__ void split2(float f0, float f1, uint32_t& h, uint32_t& l) {
    __nv_bfloat162 t = __floats2bfloat162_rn(f0, f1);
    h = *reinterpret_cast<uint32_t*>(&t);
    float r0 = __low2float(t), r1 = __high2float(t);
    __nv_bfloat162 u = __floats2bfloat162_rn(f0 - r0, f1 - r1);
    l = *reinterpret_cast<uint32_t*>(&u);
}

// ---------------------------------------------------------------------------
// Kernel 1: split W (Q,K,V weights) into hi/lo bf16.  3*131072 elems only.
// ---------------------------------------------------------------------------
#define WN ((long long)DKK * DD)           // 131072

__global__ void convert_w_kernel(const float* __restrict__ Wq,
                                 const float* __restrict__ Wk,
                                 const float* __restrict__ Wv) {
    const long long i = (long long)blockIdx.x * blockDim.x + threadIdx.x;
    const long long e = i << 2;              // 4 elems per thread
    if (e >= 3 * WN) return;
    const float* src;
    long long o = e;
    if (o < WN)          src = Wq + o;
    else if (o < 2 * WN) src = Wk + (o - WN);
    else                 src = Wv + (o - 2 * WN);
    float4 v = *(const float4*)src;
    uint32_t h0, l0, h1, l1;
    split2(v.x, v.y, h0, l0);
    split2(v.z, v.w, h1, l1);
    *(uint2*)(g_Wh + e) = make_uint2(h0, h1);
    *(uint2*)(g_Wl + e) = make_uint2(l0, l1);
}

// ---------------------------------------------------------------------------
// Kernel 2: projection GEMM  Out[m,n] = sum_k A[m,k] * W[n,k]  (bf16x3 HMMA)
// A read as fp32 and Dekker-split in-kernel (no materialized A hi/lo).
// CTA: 128 m-rows x full N=128, K chunks of 64. 256 threads (8 warps, 32x64).
// ---------------------------------------------------------------------------
#define PLD 72                                // smem stride (bf16 elems)
#define PROJ_SMEM (4 * 128 * PLD * 2)         // 73728 B

__global__ __launch_bounds__(256, 2) void proj_tc(const float* __restrict__ x,
                                                  const float* __restrict__ ctx,
                                                  const int* __restrict__ lens) {
    extern __shared__ __nv_bfloat16 psm[];
    __nv_bfloat16* sAh = psm;
    __nv_bfloat16* sAl = psm + 128 * PLD;
    __nv_bfloat16* sWh = psm + 2 * 128 * PLD;
    __nv_bfloat16* sWl = psm + 3 * 128 * PLD;
    const uint32_t aAh = smem_u32(sAh), aAl = smem_u32(sAl);
    const uint32_t aWh = smem_u32(sWh), aWl = smem_u32(sWl);

    const int which = blockIdx.y;                         // 0=Q,1=K,2=V
    const int m0cta = blockIdx.x * 128;
    const float* A = (which == 2) ? x : ctx;
    const __nv_bfloat16* Wh = g_Wh + (size_t)which * WN;
    const __nv_bfloat16* Wl = g_Wl + (size_t)which * WN;
    __nv_bfloat16* Oh = (which == 0) ? g_Qh : (which == 1) ? g_Kh : g_Vh;
    __nv_bfloat16* Ol = (which == 0) ? g_Ql : (which == 1) ? g_Kl : g_Vl;

    const int tid = threadIdx.x;
    const int w = tid >> 5, l = tid & 31;
    const int m0 = (w & 3) * 32;              // warp m offset
    const int n0 = (w >> 2) * 64;             // warp n offset

    const int arow = (l & 7) + 8 * ((l >> 3) & 1);   // A-operand lane row
    const int acol = 8 * (l >> 4);                   // A-operand lane col
    const int brow = (l & 7) + 8 * (l >> 4);         // B-operand lane row
    const int bcol = 8 * ((l >> 3) & 1);             // B-operand lane col

    float c[2][8][4];
#pragma unroll
    for (int mf = 0; mf < 2; mf++)
#pragma unroll
        for (int nf = 0; nf < 8; nf++)
#pragma unroll
            for (int e = 0; e < 4; e++) c[mf][nf][e] = 0.f;

    for (int kc = 0; kc < 16; kc++) {
        const int kg = kc * 64;
        __syncthreads();
        // A: load 128x64 fp32 chunk, split-convert to hi/lo smem.
#pragma unroll
        for (int i = 0; i < 8; i++) {
            const int idx = i * 256 + tid;               // 0..2047 float4s
            const int r = idx >> 4, c4 = (idx & 15) * 4;
            float4 v = *(const float4*)(A + (size_t)(m0cta + r) * DD + kg + c4);
            uint32_t h0, l0, h1, l1;
            split2(v.x, v.y, h0, l0);
            split2(v.z, v.w, h1, l1);
            *(uint2*)(sAh + r * PLD + c4) = make_uint2(h0, h1);
            *(uint2*)(sAl + r * PLD + c4) = make_uint2(l0, l1);
        }
        // W: copy 128x64 bf16 hi/lo chunks.
#pragma unroll
        for (int i = 0; i < 4; i++) {
            const int idx = i * 256 + tid;
            const int r = idx >> 3, cc = (idx & 7) * 8;
            const size_t gw = (size_t)r * DD + kg + cc;
            *(uint4*)(sWh + r * PLD + cc) = *(const uint4*)(Wh + gw);
            *(uint4*)(sWl + r * PLD + cc) = *(const uint4*)(Wl + gw);
        }
        __syncthreads();

#pragma unroll
        for (int ks = 0; ks < 4; ks++) {
            const int k0 = ks * 16;
            uint32_t ah[2][4], al[2][4];
#pragma unroll
            for (int mf = 0; mf < 2; mf++) {
                const uint32_t off = 2u * ((m0 + mf * 16 + arow) * PLD + k0 + acol);
                ldsm4(ah[mf], aAh + off);
                ldsm4(al[mf], aAl + off);
            }
#pragma unroll
            for (int bb = 0; bb < 4; bb++) {
                uint32_t bh[4], bl[4];
                const uint32_t off = 2u * ((n0 + bb * 16 + brow) * PLD + k0 + bcol);
                ldsm4(bh, aWh + off);
                ldsm4(bl, aWl + off);
#pragma unroll
                for (int mf = 0; mf < 2; mf++) {
                    mma16816(c[mf][2 * bb], ah[mf], bh[0], bh[1]);
                    mma16816(c[mf][2 * bb], ah[mf], bl[0], bl[1]);
                    mma16816(c[mf][2 * bb], al[mf], bh[0], bh[1]);
                    mma16816(c[mf][2 * bb + 1], ah[mf], bh[2], bh[3]);
                    mma16816(c[mf][2 * bb + 1], ah[mf], bl[2], bl[3]);
                    mma16816(c[mf][2 * bb + 1], al[mf], bh[2], bh[3]);
                }
            }
        }
    }

    // Epilogue: mask padded rows, split to bf16 hi/lo, store.
    const int batch = m0cta >> 11;
    const int len = lens[batch];
    const int tokbase = m0cta - (batch << 11);
#pragma unroll
    for (int mf = 0; mf < 2; mf++) {
        const int lr = m0 + mf * 16 + (l >> 2);
        const int gm0 = m0cta + lr, gm1 = gm0 + 8;
        const float msk0 = (tokbase + lr < len) ? 1.f : 0.f;
        const float msk1 = (tokbase + lr + 8 < len) ? 1.f : 0.f;
#pragma unroll
        for (int nf = 0; nf < 8; nf++) {
            const int col = n0 + nf * 8 + 2 * (l & 3);
            uint32_t h, lo;
            split2(c[mf][nf][0] * msk0, c[mf][nf][1] * msk0, h, lo);
            *(uint32_t*)(Oh + (size_t)gm0 * DKK + col) = h;
            *(uint32_t*)(Ol + (size_t)gm0 * DKK + col) = lo;
            split2(c[mf][nf][2] * msk1, c[mf][nf][3] * msk1, h, lo);
            *(uint32_t*)(Oh + (size_t)gm1 * DKK + col) = h;
            *(uint32_t*)(Ol + (size_t)gm1 * DKK + col) = lo;
        }
    }
}

// ---------------------------------------------------------------------------
// Kernel 3: flash attention, bf16x3 HMMA, register-resident softmax & P.
// CTA: 64 queries, key tiles of 64, dk=128. 128 threads (4 warps x 16 rows).
// Task remap: bids k and k+148 co-reside on one SM (LUT[bid%148] placement);
// give complementary-work (qt) pairs to co-residents, mid-weight tasks to the
// 40 solo-SM bids (108..147).
// ---------------------------------------------------------------------------
#define ALD 136                               // smem stride (bf16 elems)
#define TSZ (64 * ALD)                        // one tile, elems
#define ATTN_SMEM (6 * TSZ * 2)               // 104448 B

__global__ __launch_bounds__(128, 2) void attn_tc(const int* __restrict__ lens,
                                                  float* __restrict__ out) {
    extern __shared__ __nv_bfloat16 asm_[];
    __nv_bfloat16* sQh = asm_;
    __nv_bfloat16* sQl = asm_ + TSZ;
    __nv_bfloat16* sKh = asm_ + 2 * TSZ;
    __nv_bfloat16* sKl = asm_ + 3 * TSZ;
    __nv_bfloat16* sVh = asm_ + 4 * TSZ;
    __nv_bfloat16* sVl = asm_ + 5 * TSZ;
    const uint32_t aQh = smem_u32(sQh), aQl = smem_u32(sQl);
    const uint32_t aKh = smem_u32(sKh), aKl = smem_u32(sKl);
    const uint32_t aVh = smem_u32(sVh), aVl = smem_u32(sVl);

    // ---- balanced task remap ----
    const int f = blockIdx.x;                  // 0..255
    int r;
    if (f < 76)        r = f;                  // pair member A (heavy side)
    else if (f < 108)  r = 40 + f;             // pair member A (ranks 116..147)
    else if (f < 148)  r = f - 32;             // solo SMs: ranks 76..115 (mid)
    else               r = 403 - f;            // pair member B (light side)
    const int qt = 31 - (r >> 3);              // work descends with rank
    const int b  = r & 7;

    const int q0 = qt * 64;
    const int len = lens[b];
    const int tid = threadIdx.x;
    const int w = tid >> 5, l = tid & 31;
    const int m0 = w * 16;

    const int arow = (l & 7) + 8 * ((l >> 3) & 1);
    const int acol = 8 * (l >> 4);
    const int brow = (l & 7) + 8 * (l >> 4);
    const int bcol = 8 * ((l >> 3) & 1);

    // Load Q tile (64 x 128) hi/lo
#pragma unroll
    for (int i = 0; i < 8; i++) {
        const int idx = i * 128 + tid;
        const int rr = idx >> 4, cc = (idx & 15) * 8;
        const size_t g = (size_t)(b * SS + q0 + rr) * DKK + cc;
        *(uint4*)(sQh + rr * ALD + cc) = *(const uint4*)(g_Qh + g);
        *(uint4*)(sQl + rr * ALD + cc) = *(const uint4*)(g_Ql + g);
    }

    float o[16][4];
#pragma unroll
    for (int nf = 0; nf < 16; nf++)
#pragma unroll
        for (int e = 0; e < 4; e++) o[nf][e] = 0.f;
    float mI0 = -1e30f, mI1 = -1e30f, lI0 = 0.f, lI1 = 0.f;

    const int r0 = q0 + m0 + (l >> 2);
    const int r1 = r0 + 8;
    const int jt_max = min(qt, (len - 1) >> 6);
    const float scale = 0.08838834764831845f;      // 1/sqrt(128)

    for (int jt = 0; jt <= jt_max; jt++) {
        const int j0 = jt * 64;
        __syncthreads();
        // Load K/V tiles (64 x 128) hi/lo
#pragma unroll
        for (int i = 0; i < 8; i++) {
            const int idx = i * 128 + tid;
            const int rr = idx >> 4, cc = (idx & 15) * 8;
            const size_t g = (size_t)(b * SS + j0 + rr) * DKK + cc;
            *(uint4*)(sKh + rr * ALD + cc) = *(const uint4*)(g_Kh + g);
            *(uint4*)(sKl + rr * ALD + cc) = *(const uint4*)(g_Kl + g);
            *(uint4*)(sVh + rr * ALD + cc) = *(const uint4*)(g_Vh + g);
            *(uint4*)(sVl + rr * ALD + cc) = *(const uint4*)(g_Vl + g);
        }
        __syncthreads();

        // ---- S = Q K^T (3-term split) ----
        float s[8][4];
#pragma unroll
        for (int nf = 0; nf < 8; nf++)
#pragma unroll
            for (int e = 0; e < 4; e++) s[nf][e] = 0.f;

#pragma unroll
        for (int ks = 0; ks < 8; ks++) {
            const int k0 = ks * 16;
            uint32_t ah[4], al[4];
            const uint32_t offA = 2u * ((m0 + arow) * ALD + k0 + acol);
            ldsm4(ah, aQh + offA);
            ldsm4(al, aQl + offA);
#pragma unroll
            for (int bb = 0; bb < 4; bb++) {
                uint32_t bh[4], bl[4];
                const uint32_t offB = 2u * ((bb * 16 + brow) * ALD + k0 + bcol);
                ldsm4(bh, aKh + offB);
                ldsm4(bl, aKl + offB);
                mma16816(s[2 * bb], ah, bh[0], bh[1]);
                mma16816(s[2 * bb], ah, bl[0], bl[1]);
                mma16816(s[2 * bb], al, bh[0], bh[1]);
                mma16816(s[2 * bb + 1], ah, bh[2], bh[3]);
                mma16816(s[2 * bb + 1], ah, bl[2], bl[3]);
                mma16816(s[2 * bb + 1], al, bh[2], bh[3]);
            }
        }

        // ---- scale + masks ----
        if (j0 + 63 <= q0 && j0 + 63 < len) {
#pragma unroll
            for (int nf = 0; nf < 8; nf++)
#pragma unroll
                for (int e = 0; e < 4; e++) s[nf][e] *= scale;
        } else {
#pragma unroll
            for (int nf = 0; nf < 8; nf++) {
                const int cj = j0 + nf * 8 + 2 * (l & 3);
                s[nf][0] = (cj     <= r0 && cj     < len) ? s[nf][0] * scale : -1e30f;
                s[nf][1] = (cj + 1 <= r0 && cj + 1 < len) ? s[nf][1] * scale : -1e30f;
                s[nf][2] = (cj     <= r1 && cj     < len) ? s[nf][2] * scale : -1e30f;
                s[nf][3] = (cj + 1 <= r1 && cj + 1 < len) ? s[nf][3] * scale : -1e30f;
            }
        }

        // ---- online softmax (register rows; reduce across quad lanes) ----
        float mx0 = -1e30f, mx1 = -1e30f;
#pragma unroll
        for (int nf = 0; nf < 8; nf++) {
            mx0 = fmaxf(mx0, fmaxf(s[nf][0], s[nf][1]));
            mx1 = fmaxf(mx1, fmaxf(s[nf][2], s[nf][3]));
        }
        mx0 = fmaxf(mx0, __shfl_xor_sync(0xffffffffu, mx0, 1));
        mx0 = fmaxf(mx0, __shfl_xor_sync(0xffffffffu, mx0, 2));
        mx1 = fmaxf(mx1, __shfl_xor_sync(0xffffffffu, mx1, 1));
        mx1 = fmaxf(mx1, __shfl_xor_sync(0xffffffffu, mx1, 2));

        const float mn0 = fmaxf(mI0, mx0), mn1 = fmaxf(mI1, mx1);
        const float f0 = __expf(mI0 - mn0), f1 = __expf(mI1 - mn1);
        mI0 = mn0; mI1 = mn1;

        float sum0 = 0.f, sum1 = 0.f;
#pragma unroll
        for (int nf = 0; nf < 8; nf++) {
            s[nf][0] = __expf(s[nf][0] - mn0);
            s[nf][1] = __expf(s[nf][1] - mn0);
            s[nf][2] = __expf(s[nf][2] - mn1);
            s[nf][3] = __expf(s[nf][3] - mn1);
            sum0 += s[nf][0] + s[nf][1];
            sum1 += s[nf][2] + s[nf][3];
        }
        sum0 += __shfl_xor_sync(0xffffffffu, sum0, 1);
        sum0 += __shfl_xor_sync(0xffffffffu, sum0, 2);
        sum1 += __shfl_xor_sync(0xffffffffu, sum1, 1);
        sum1 += __shfl_xor_sync(0xffffffffu, sum1, 2);
        lI0 = lI0 * f0 + sum0;
        lI1 = lI1 * f1 + sum1;

        // rescale output accumulators
#pragma unroll
        for (int nf = 0; nf < 16; nf++) {
            o[nf][0] *= f0; o[nf][1] *= f0;
            o[nf][2] *= f1; o[nf][3] *= f1;
        }

        // pack P into A-fragments (c-layout == a-layout), hi + lo
        uint32_t Ph[4][4], Pl[4][4];
#pragma unroll
        for (int t = 0; t < 4; t++) {
            split2(s[2 * t][0],     s[2 * t][1],     Ph[t][0], Pl[t][0]);
            split2(s[2 * t][2],     s[2 * t][3],     Ph[t][1], Pl[t][1]);
            split2(s[2 * t + 1][0], s[2 * t + 1][1], Ph[t][2], Pl[t][2]);
            split2(s[2 * t + 1][2], s[2 * t + 1][3], Ph[t][3], Pl[t][3]);
        }

        // ---- O += P V (3-term split, V via ldmatrix.trans) ----
#pragma unroll
        for (int t = 0; t < 4; t++) {
            const int jr = t * 16;
#pragma unroll
            for (int db = 0; db < 8; db++) {
                uint32_t vh[4], vl[4];
                const uint32_t offV = 2u * ((jr + arow) * ALD + db * 16 + acol);
                ldsm4t(vh, aVh + offV);
                ldsm4t(vl, aVl + offV);
                mma16816(o[2 * db], Ph[t], vh[0], vh[1]);
                mma16816(o[2 * db], Ph[t], vl[0], vl[1]);
                mma16816(o[2 * db], Pl[t], vh[0], vh[1]);
                mma16816(o[2 * db + 1], Ph[t], vh[2], vh[3]);
                mma16816(o[2 * db + 1], Ph[t], vl[2], vl[3]);
                mma16816(o[2 * db + 1], Pl[t], vh[2], vh[3]);
            }
        }
    }

    // ---- epilogue: O /= l ----
    const float inv0 = 1.f / lI0, inv1 = 1.f / lI1;
#pragma unroll
    for (int nf = 0; nf < 16; nf++) {
        const int col = nf * 8 + 2 * (l & 3);
        *(float2*)(out + ((size_t)b * SS + r0) * DKK + col) =
            make_float2(o[nf][0] * inv0, o[nf][1] * inv0);
        *(float2*)(out + ((size_t)b * SS + r1) * DKK + col) =
            make_float2(o[nf][2] * inv1, o[nf][3] * inv1);
    }
}

// ---------------------------------------------------------------------------
extern "C" void kernel_launch(void* const* d_in, const int* in_sizes, int n_in,
                              void* d_out, int out_size)
{
    const float* x   = (const float*)d_in[0];
    const float* ctx = (const float*)d_in[1];
    const float* Wq  = (const float*)d_in[2];
    const float* Wk  = (const float*)d_in[3];
    const float* Wv  = (const float*)d_in[4];
    const int* lens  = (const int*)d_in[5];
    float* out = (float*)d_out;

    cudaFuncSetAttribute(proj_tc, cudaFuncAttributeMaxDynamicSharedMemorySize,
                         PROJ_SMEM);
    cudaFuncSetAttribute(attn_tc, cudaFuncAttributeMaxDynamicSharedMemorySize,
                         ATTN_SMEM);

    convert_w_kernel<<<384, 256>>>(Wq, Wk, Wv);

    dim3 gp(NTOK / 128, 3);
    proj_tc<<<gp, 256, PROJ_SMEM>>>(x, ctx, lens);

    attn_tc<<<256, 128, ATTN_SMEM>>>(lens, out);
}